// round 2
// baseline (speedup 1.0000x reference)
#include <cuda_runtime.h>
#include <math.h>

#define T_TOK 8192
#define D_DIM 1024
#define H_DIM 2048
#define E_NUM 8
#define NA (T_TOK * 2)

// ---------------- scratch (device globals; no allocation) ----------------
__device__ int   g_cnt[E_NUM];
__device__ int   g_off[E_NUM];
__device__ int   g_cur[E_NUM];
__device__ int   g_sel[NA];
__device__ float g_prob[NA];
__device__ int   g_rows[NA];
__device__ float g_rprob[NA];
__device__ float g_h[(size_t)NA * H_DIM];   // 128 MB intermediate

// ---------------- init: zero counters ----------------
__global__ void init_kernel() {
    int i = threadIdx.x;
    if (i < E_NUM) { g_cnt[i] = 0; g_cur[i] = 0; }
}

// ---------------- zero output ----------------
__global__ void zero_out_kernel(float* __restrict__ out, size_t n4) {
    size_t i = (size_t)blockIdx.x * blockDim.x + threadIdx.x;
    size_t stride = (size_t)gridDim.x * blockDim.x;
    float4 z = make_float4(0.f, 0.f, 0.f, 0.f);
    for (; i < n4; i += stride)
        reinterpret_cast<float4*>(out)[i] = z;
}

// ---------------- gating: warp per token ----------------
__global__ void gate_kernel(const float* __restrict__ x, const float* __restrict__ wg) {
    int warp = (blockIdx.x * blockDim.x + threadIdx.x) >> 5;
    int lane = threadIdx.x & 31;
    if (warp >= T_TOK) return;
    const float* xr = x + (size_t)warp * D_DIM;
    float acc[E_NUM];
#pragma unroll
    for (int e = 0; e < E_NUM; e++) acc[e] = 0.f;
    for (int d = lane; d < D_DIM; d += 32) {
        float xv = xr[d];
        const float* w = wg + (size_t)d * E_NUM;
#pragma unroll
        for (int e = 0; e < E_NUM; e++) acc[e] += xv * w[e];
    }
#pragma unroll
    for (int e = 0; e < E_NUM; e++) {
#pragma unroll
        for (int o = 16; o > 0; o >>= 1)
            acc[e] += __shfl_xor_sync(0xffffffff, acc[e], o);
    }
    if (lane == 0) {
        float best = -1e30f, sec = -1e30f;
        int bi = 0, si = 0;
#pragma unroll
        for (int e = 0; e < E_NUM; e++) {
            float v = acc[e];
            if (v > best) { sec = best; si = bi; best = v; bi = e; }
            else if (v > sec) { sec = v; si = e; }
        }
        float p0 = 1.f / (1.f + expf(sec - best));   // softmax over [best, sec]
        g_sel[warp * 2]     = bi;
        g_sel[warp * 2 + 1] = si;
        g_prob[warp * 2]     = p0;
        g_prob[warp * 2 + 1] = 1.f - p0;
        atomicAdd(&g_cnt[bi], 1);
        atomicAdd(&g_cnt[si], 1);
    }
}

// ---------------- exclusive scan over 8 counts ----------------
__global__ void offsets_kernel() {
    if (threadIdx.x == 0) {
        int r = 0;
        for (int e = 0; e < E_NUM; e++) {
            g_off[e] = r;
            g_cur[e] = r;
            r += g_cnt[e];
        }
    }
}

// ---------------- scatter tokens into per-expert rows ----------------
__global__ void scatter_kernel() {
    int t = blockIdx.x * blockDim.x + threadIdx.x;
    if (t >= T_TOK) return;
#pragma unroll
    for (int k = 0; k < 2; k++) {
        int e = g_sel[t * 2 + k];
        int pos = atomicAdd(&g_cur[e], 1);
        g_rows[pos]  = t;
        g_rprob[pos] = g_prob[t * 2 + k];
    }
}

// ---------------- GEMM1: h = silu(X@W1) * (X@W3), gathered rows ----------------
// BM=128, BN=64, BK=16, TM=8, TN=4, 256 threads, double-buffered smem.
__global__ __launch_bounds__(256) void gemm1_kernel(
    const float* __restrict__ x,
    const float* __restrict__ w1,
    const float* __restrict__ w3)
{
    const int BM = 128, BN = 64, BK = 16, TM = 8, TN = 4;
    const int NT = D_DIM / BK;   // 64 k-tiles
    int e  = blockIdx.y;
    int Me = g_cnt[e];
    int m0 = blockIdx.x * BM;
    if (m0 >= Me) return;
    int n0   = blockIdx.z * BN;
    int base = g_off[e];
    const float* W1 = w1 + (size_t)e * D_DIM * H_DIM;
    const float* W3 = w3 + (size_t)e * D_DIM * H_DIM;

    __shared__ __align__(16) float As[2][BK][BM];
    __shared__ __align__(16) float B1s[2][BK][BN];
    __shared__ __align__(16) float B3s[2][BK][BN];

    int tid = threadIdx.x;
    int tx = tid & 15;        // col group  (tx*TN)
    int ty = tid >> 4;        // row group  (ty*TM)

    // A-load assignments: 2 float4 per thread per k-tile
    int arow[2], akv[2];
    const float* aptr[2];
#pragma unroll
    for (int i = 0; i < 2; i++) {
        int idx = tid + i * 256;
        arow[i] = idx >> 2;
        akv[i]  = idx & 3;
        int m = m0 + arow[i];
        aptr[i] = (m < Me) ? (x + (size_t)g_rows[base + m] * D_DIM + akv[i] * 4) : nullptr;
    }
    int bkrow = tid >> 4;          // 0..15
    int bnv   = (tid & 15) * 4;    // 0..60
    const float* b1p = W1 + (size_t)bkrow * H_DIM + n0 + bnv;
    const float* b3p = W3 + (size_t)bkrow * H_DIM + n0 + bnv;

    float acc1[TM][TN];
    float acc3[TM][TN];
#pragma unroll
    for (int i = 0; i < TM; i++)
#pragma unroll
        for (int j = 0; j < TN; j++) { acc1[i][j] = 0.f; acc3[i][j] = 0.f; }

    // -------- prologue: load tile 0 --------
    float4 av[2], b1v, b3v;
#pragma unroll
    for (int i = 0; i < 2; i++)
        av[i] = aptr[i] ? *reinterpret_cast<const float4*>(aptr[i])
                        : make_float4(0.f, 0.f, 0.f, 0.f);
    b1v = *reinterpret_cast<const float4*>(b1p);
    b3v = *reinterpret_cast<const float4*>(b3p);
#pragma unroll
    for (int i = 0; i < 2; i++) {
        As[0][akv[i] * 4 + 0][arow[i]] = av[i].x;
        As[0][akv[i] * 4 + 1][arow[i]] = av[i].y;
        As[0][akv[i] * 4 + 2][arow[i]] = av[i].z;
        As[0][akv[i] * 4 + 3][arow[i]] = av[i].w;
    }
    *reinterpret_cast<float4*>(&B1s[0][bkrow][bnv]) = b1v;
    *reinterpret_cast<float4*>(&B3s[0][bkrow][bnv]) = b3v;
    __syncthreads();

    int buf = 0;
    for (int t = 0; t < NT; t++) {
        // issue next-tile global loads first (latency hidden by compute)
        if (t + 1 < NT) {
            int k0 = (t + 1) * BK;
#pragma unroll
            for (int i = 0; i < 2; i++)
                av[i] = aptr[i] ? *reinterpret_cast<const float4*>(aptr[i] + k0)
                                : make_float4(0.f, 0.f, 0.f, 0.f);
            b1v = *reinterpret_cast<const float4*>(b1p + (size_t)k0 * H_DIM);
            b3v = *reinterpret_cast<const float4*>(b3p + (size_t)k0 * H_DIM);
        }

#pragma unroll
        for (int k = 0; k < BK; k++) {
            float4 a0  = *reinterpret_cast<const float4*>(&As[buf][k][ty * TM]);
            float4 a1  = *reinterpret_cast<const float4*>(&As[buf][k][ty * TM + 4]);
            float4 bb1 = *reinterpret_cast<const float4*>(&B1s[buf][k][tx * TN]);
            float4 bb3 = *reinterpret_cast<const float4*>(&B3s[buf][k][tx * TN]);
            float a[TM]   = {a0.x, a0.y, a0.z, a0.w, a1.x, a1.y, a1.z, a1.w};
            float b1r[TN] = {bb1.x, bb1.y, bb1.z, bb1.w};
            float b3r[TN] = {bb3.x, bb3.y, bb3.z, bb3.w};
#pragma unroll
            for (int i = 0; i < TM; i++)
#pragma unroll
                for (int j = 0; j < TN; j++) {
                    acc1[i][j] += a[i] * b1r[j];
                    acc3[i][j] += a[i] * b3r[j];
                }
        }

        if (t + 1 < NT) {
            int nb = buf ^ 1;
#pragma unroll
            for (int i = 0; i < 2; i++) {
                As[nb][akv[i] * 4 + 0][arow[i]] = av[i].x;
                As[nb][akv[i] * 4 + 1][arow[i]] = av[i].y;
                As[nb][akv[i] * 4 + 2][arow[i]] = av[i].z;
                As[nb][akv[i] * 4 + 3][arow[i]] = av[i].w;
            }
            *reinterpret_cast<float4*>(&B1s[nb][bkrow][bnv]) = b1v;
            *reinterpret_cast<float4*>(&B3s[nb][bkrow][bnv]) = b3v;
            __syncthreads();
            buf = nb;
        }
    }

#pragma unroll
    for (int i = 0; i < TM; i++) {
        int m = m0 + ty * TM + i;
        if (m < Me) {
            float4 hv;
            float z;
            z = acc1[i][0]; hv.x = z / (1.f + expf(-z)) * acc3[i][0];
            z = acc1[i][1]; hv.y = z / (1.f + expf(-z)) * acc3[i][1];
            z = acc1[i][2]; hv.z = z / (1.f + expf(-z)) * acc3[i][2];
            z = acc1[i][3]; hv.w = z / (1.f + expf(-z)) * acc3[i][3];
            *reinterpret_cast<float4*>(&g_h[(size_t)(base + m) * H_DIM + n0 + tx * TN]) = hv;
        }
    }
}

// ---------------- GEMM2: y = h @ W2, epilogue out[t] += p*y ----------------
// BM=128, BN=128, BK=16, TM=8, TN=8, 256 threads, double-buffered smem.
__global__ __launch_bounds__(256) void gemm2_kernel(
    const float* __restrict__ w2, float* __restrict__ out)
{
    const int BM = 128, BN = 128, BK = 16, TM = 8, TN = 8;
    const int NT = H_DIM / BK;   // 128 k-tiles
    int e  = blockIdx.y;
    int Me = g_cnt[e];
    int m0 = blockIdx.x * BM;
    if (m0 >= Me) return;
    int n0   = blockIdx.z * BN;
    int base = g_off[e];
    const float* W2 = w2 + (size_t)e * H_DIM * D_DIM;

    __shared__ __align__(16) float As[2][BK][BM];
    __shared__ __align__(16) float Bs[2][BK][BN];

    int tid = threadIdx.x;
    int tx = tid & 15;    // col group (tx*TN), 0..15
    int ty = tid >> 4;    // row group (ty*TM), 0..15

    // A loads: BM*BK/4 = 512 float4 / 256 thr = 2 each
    int arow[2], akv[2];
    const float* aptr[2];
#pragma unroll
    for (int i = 0; i < 2; i++) {
        int idx = tid + i * 256;
        arow[i] = idx >> 2;
        akv[i]  = idx & 3;
        int m = m0 + arow[i];
        aptr[i] = (m < Me) ? (g_h + (size_t)(base + m) * H_DIM + akv[i] * 4) : nullptr;
    }
    // B loads: BK*BN/4 = 512 float4 / 256 thr = 2 each
    int bkr[2], bnv[2];
    const float* bptr[2];
#pragma unroll
    for (int i = 0; i < 2; i++) {
        int idx = tid + i * 256;
        bkr[i] = idx >> 5;          // 0..15
        bnv[i] = (idx & 31) * 4;    // 0..124
        bptr[i] = W2 + (size_t)bkr[i] * D_DIM + n0 + bnv[i];
    }

    float acc[TM][TN];
#pragma unroll
    for (int i = 0; i < TM; i++)
#pragma unroll
        for (int j = 0; j < TN; j++) acc[i][j] = 0.f;

    // -------- prologue --------
    float4 av[2], bv[2];
#pragma unroll
    for (int i = 0; i < 2; i++) {
        av[i] = aptr[i] ? *reinterpret_cast<const float4*>(aptr[i])
                        : make_float4(0.f, 0.f, 0.f, 0.f);
        bv[i] = *reinterpret_cast<const float4*>(bptr[i]);
    }
#pragma unroll
    for (int i = 0; i < 2; i++) {
        As[0][akv[i] * 4 + 0][arow[i]] = av[i].x;
        As[0][akv[i] * 4 + 1][arow[i]] = av[i].y;
        As[0][akv[i] * 4 + 2][arow[i]] = av[i].z;
        As[0][akv[i] * 4 + 3][arow[i]] = av[i].w;
        *reinterpret_cast<float4*>(&Bs[0][bkr[i]][bnv[i]]) = bv[i];
    }
    __syncthreads();

    int buf = 0;
    for (int t = 0; t < NT; t++) {
        if (t + 1 < NT) {
            int k0 = (t + 1) * BK;
#pragma unroll
            for (int i = 0; i < 2; i++) {
                av[i] = aptr[i] ? *reinterpret_cast<const float4*>(aptr[i] + k0)
                                : make_float4(0.f, 0.f, 0.f, 0.f);
                bv[i] = *reinterpret_cast<const float4*>(bptr[i] + (size_t)k0 * D_DIM);
            }
        }

#pragma unroll
        for (int k = 0; k < BK; k++) {
            float4 a0 = *reinterpret_cast<const float4*>(&As[buf][k][ty * TM]);
            float4 a1 = *reinterpret_cast<const float4*>(&As[buf][k][ty * TM + 4]);
            float4 b0 = *reinterpret_cast<const float4*>(&Bs[buf][k][tx * TN]);
            float4 b1 = *reinterpret_cast<const float4*>(&Bs[buf][k][tx * TN + 4]);
            float a[TM] = {a0.x, a0.y, a0.z, a0.w, a1.x, a1.y, a1.z, a1.w};
            float b[TN] = {b0.x, b0.y, b0.z, b0.w, b1.x, b1.y, b1.z, b1.w};
#pragma unroll
            for (int i = 0; i < TM; i++)
#pragma unroll
                for (int j = 0; j < TN; j++) acc[i][j] += a[i] * b[j];
        }

        if (t + 1 < NT) {
            int nb = buf ^ 1;
#pragma unroll
            for (int i = 0; i < 2; i++) {
                As[nb][akv[i] * 4 + 0][arow[i]] = av[i].x;
                As[nb][akv[i] * 4 + 1][arow[i]] = av[i].y;
                As[nb][akv[i] * 4 + 2][arow[i]] = av[i].z;
                As[nb][akv[i] * 4 + 3][arow[i]] = av[i].w;
                *reinterpret_cast<float4*>(&Bs[nb][bkr[i]][bnv[i]]) = bv[i];
            }
            __syncthreads();
            buf = nb;
        }
    }

#pragma unroll
    for (int i = 0; i < TM; i++) {
        int m = m0 + ty * TM + i;
        if (m < Me) {
            int pos = base + m;
            int t   = g_rows[pos];
            float p = g_rprob[pos];
            float* op = out + (size_t)t * D_DIM + n0 + tx * TN;
#pragma unroll
            for (int j = 0; j < TN; j++)
                atomicAdd(op + j, p * acc[i][j]);
        }
    }
}

// ---------------- launch ----------------
extern "C" void kernel_launch(void* const* d_in, const int* in_sizes, int n_in,
                              void* d_out, int out_size) {
    const float* x  = (const float*)d_in[0];   // (B,S,D)
    const float* wg = (const float*)d_in[1];   // (D,E)
    const float* w1 = (const float*)d_in[2];   // (E,D,H)
    const float* w3 = (const float*)d_in[3];   // (E,D,H)
    const float* w2 = (const float*)d_in[4];   // (E,H,D)
    float* out = (float*)d_out;

    (void)in_sizes; (void)n_in;

    init_kernel<<<1, 32>>>();
    zero_out_kernel<<<1024, 256>>>(out, (size_t)out_size / 4);
    gate_kernel<<<(T_TOK * 32 + 255) / 256, 256>>>(x, wg);
    offsets_kernel<<<1, 32>>>();
    scatter_kernel<<<(T_TOK + 255) / 256, 256>>>();

    dim3 g1(T_TOK / 128, E_NUM, H_DIM / 64);   // (64, 8, 32)
    gemm1_kernel<<<g1, 256>>>(x, w1, w3);

    dim3 g2(T_TOK / 128, E_NUM, D_DIM / 128);  // (64, 8, 8)
    gemm2_kernel<<<g2, 256>>>(w2, out);
}

// round 5
// speedup vs baseline: 3.7061x; 3.7061x over previous
#include <cuda_runtime.h>
#include <math.h>
#include <stdint.h>

#define T_TOK 8192
#define D_DIM 1024
#define H_DIM 2048
#define E_NUM 8
#define NA (T_TOK * 2)

// ---------------- scratch (device globals; no allocation) ----------------
__device__ int   g_cnt[E_NUM];
__device__ int   g_off[E_NUM];
__device__ int   g_cur[E_NUM];
__device__ int   g_sel[NA];
__device__ float g_prob[NA];
__device__ int   g_rows[NA];
__device__ int   g_tokpos[NA];
__device__ float g_xc[(size_t)T_TOK * D_DIM];                //  32 MB tf32 x
__device__ float g_t1[(size_t)NA * H_DIM];                   // 128 MB raw X@W1
__device__ float g_t3[(size_t)NA * H_DIM];                   // 128 MB raw X@W3
__device__ float g_h [(size_t)NA * H_DIM];                   // 128 MB silu product (tf32)
__device__ float g_y [(size_t)NA * D_DIM];                   //  64 MB expert outputs
__device__ float g_w1T[(size_t)E_NUM * H_DIM * D_DIM];       //  64 MB [e][h][d] tf32
__device__ float g_w3T[(size_t)E_NUM * H_DIM * D_DIM];       //  64 MB [e][h][d] tf32
__device__ float g_w2T[(size_t)E_NUM * D_DIM * H_DIM];       //  64 MB [e][d][h] tf32

// ================= helpers =================
__device__ __forceinline__ uint32_t smem_u32(const void* p) {
    uint32_t a;
    asm("{ .reg .u64 t; cvta.to.shared.u64 t, %1; cvt.u32.u64 %0, t; }" : "=r"(a) : "l"(p));
    return a;
}
__device__ __forceinline__ uint32_t f2tf32(float x) {
    uint32_t u;
    asm("cvt.rna.tf32.f32 %0, %1;" : "=r"(u) : "f"(x));
    return u;
}

#define CP_ASYNC16(dst, src) \
    asm volatile("cp.async.cg.shared.global [%0], [%1], 16;" :: "r"(dst), "l"(src) : "memory")
#define CP_COMMIT() asm volatile("cp.async.commit_group;" ::: "memory")
#define CP_WAIT1()  asm volatile("cp.async.wait_group 1;" ::: "memory")
#define CP_WAIT0()  asm volatile("cp.async.wait_group 0;" ::: "memory")

#define LDSM_X4(r, addr) \
    asm volatile("ldmatrix.sync.aligned.m8n8.x4.shared.b16 {%0,%1,%2,%3}, [%4];" \
        : "=r"((r)[0]), "=r"((r)[1]), "=r"((r)[2]), "=r"((r)[3]) : "r"(addr))
#define LDSM_X2(r, addr) \
    asm volatile("ldmatrix.sync.aligned.m8n8.x2.shared.b16 {%0,%1}, [%2];" \
        : "=r"((r)[0]), "=r"((r)[1]) : "r"(addr))

#define MMA_TF32(d, a, b) \
    asm volatile("mma.sync.aligned.m16n8k8.row.col.f32.tf32.tf32.f32 " \
        "{%0,%1,%2,%3}, {%4,%5,%6,%7}, {%8,%9}, {%0,%1,%2,%3};" \
        : "+f"((d)[0]), "+f"((d)[1]), "+f"((d)[2]), "+f"((d)[3]) \
        : "r"((a)[0]), "r"((a)[1]), "r"((a)[2]), "r"((a)[3]), "r"((b)[0]), "r"((b)[1]))

// ---------------- init ----------------
__global__ void init_kernel() {
    int i = threadIdx.x;
    if (i < E_NUM) { g_cnt[i] = 0; g_cur[i] = 0; }
}

// ---------------- x -> tf32 copy ----------------
__global__ void cvt_x_kernel(const float* __restrict__ x) {
    size_t i = ((size_t)blockIdx.x * blockDim.x + threadIdx.x) * 4;
    float4 v = *reinterpret_cast<const float4*>(x + i);
    uint4 o;
    o.x = f2tf32(v.x); o.y = f2tf32(v.y); o.z = f2tf32(v.z); o.w = f2tf32(v.w);
    *reinterpret_cast<uint4*>(g_xc + i) = o;
}

// ---------------- weight transpose + tf32 round: [E][R][C] -> [E][C][R] ----------------
__global__ void transpose_cvt_kernel(const float* __restrict__ src, float* __restrict__ dst,
                                     int R, int C) {
    __shared__ float tile[32][33];
    size_t eoff = (size_t)blockIdx.z * R * C;
    src += eoff; dst += eoff;
    int c0 = blockIdx.x * 32, r0 = blockIdx.y * 32;
    int tx = threadIdx.x, ty = threadIdx.y;
#pragma unroll
    for (int i = 0; i < 4; i++)
        tile[ty + i * 8][tx] = src[(size_t)(r0 + ty + i * 8) * C + c0 + tx];
    __syncthreads();
#pragma unroll
    for (int i = 0; i < 4; i++)
        dst[(size_t)(c0 + ty + i * 8) * R + r0 + tx] =
            __uint_as_float(f2tf32(tile[tx][ty + i * 8]));
}

// ---------------- gating: warp per token (exact fp32) ----------------
__global__ void gate_kernel(const float* __restrict__ x, const float* __restrict__ wg) {
    int warp = (blockIdx.x * blockDim.x + threadIdx.x) >> 5;
    int lane = threadIdx.x & 31;
    if (warp >= T_TOK) return;
    const float* xr = x + (size_t)warp * D_DIM;
    float acc[E_NUM];
#pragma unroll
    for (int e = 0; e < E_NUM; e++) acc[e] = 0.f;
    for (int d = lane; d < D_DIM; d += 32) {
        float xv = xr[d];
        const float* w = wg + (size_t)d * E_NUM;
#pragma unroll
        for (int e = 0; e < E_NUM; e++) acc[e] += xv * w[e];
    }
#pragma unroll
    for (int e = 0; e < E_NUM; e++) {
#pragma unroll
        for (int o = 16; o > 0; o >>= 1)
            acc[e] += __shfl_xor_sync(0xffffffff, acc[e], o);
    }
    if (lane == 0) {
        float best = -1e30f, sec = -1e30f;
        int bi = 0, si = 0;
#pragma unroll
        for (int e = 0; e < E_NUM; e++) {
            float v = acc[e];
            if (v > best) { sec = best; si = bi; best = v; bi = e; }
            else if (v > sec) { sec = v; si = e; }
        }
        float p0 = 1.f / (1.f + expf(sec - best));
        g_sel[warp * 2]      = bi;
        g_sel[warp * 2 + 1]  = si;
        g_prob[warp * 2]     = p0;
        g_prob[warp * 2 + 1] = 1.f - p0;
        atomicAdd(&g_cnt[bi], 1);
        atomicAdd(&g_cnt[si], 1);
    }
}

__global__ void offsets_kernel() {
    if (threadIdx.x == 0) {
        int r = 0;
        for (int e = 0; e < E_NUM; e++) { g_off[e] = r; g_cur[e] = r; r += g_cnt[e]; }
    }
}

__global__ void scatter_kernel() {
    int t = blockIdx.x * blockDim.x + threadIdx.x;
    if (t >= T_TOK) return;
#pragma unroll
    for (int k = 0; k < 2; k++) {
        int e = g_sel[t * 2 + k];
        int pos = atomicAdd(&g_cur[e], 1);
        g_rows[pos]      = t;
        g_tokpos[t * 2 + k] = pos;
    }
}

// ================= tf32 mma.sync GEMM =================
// CTA tile 128x256x32, 8 warps (2m x 4n), warp tile 64x64 (4 mfrag x 8 nfrag m16n8k8).
// A smem: [128 rows][32 k] 128B rows, SW128-swizzled. B smem: [256 n-rows][32 k] same.
// Double-buffered cp.async. Raw fp32 output C[base+row][Ntot].
#define GM_SMEM (2 * 49152)
__global__ __launch_bounds__(256, 1) void gemm_mma(
    const float* __restrict__ Abase,
    const float* __restrict__ Bmat0,
    const float* __restrict__ Bmat1,
    float* __restrict__ Cmat0,
    float* __restrict__ Cmat1,
    int K, int Ntot, int nblk_per_mat, int gather)
{
    int e  = blockIdx.y;
    int Me = g_cnt[e];
    int m0 = blockIdx.x * 128;
    if (m0 >= Me) return;
    int zz    = blockIdx.z;
    int which = zz / nblk_per_mat;
    int nblk  = zz - which * nblk_per_mat;
    const float* B = (which ? Bmat1 : Bmat0) + (size_t)e * Ntot * K;
    float* C = which ? Cmat1 : Cmat0;
    int base = g_off[e];
    int n0   = nblk * 256;

    extern __shared__ char ds[];
    uint32_t sb = smem_u32(ds);
    int tid = threadIdx.x, lane = tid & 31, wid = tid >> 5;
    int wm = wid & 1, wn = wid >> 1;

    // ---- loader assignments (fixed per thread) ----
    const float* aSrc[4]; uint32_t aDst[4];
#pragma unroll
    for (int j = 0; j < 4; j++) {
        int v = tid + j * 256, q = v & 7, m = v >> 3;
        int mg = m0 + m; if (mg > Me - 1) mg = Me - 1;
        int row = gather ? g_rows[base + mg] : (base + mg);
        aSrc[j] = Abase + (size_t)row * K + q * 4;
        aDst[j] = sb + (uint32_t)(m * 128) + (uint32_t)((q ^ (m & 7)) << 4);
    }
    const float* bSrc[8]; uint32_t bDst[8];
#pragma unroll
    for (int j = 0; j < 8; j++) {
        int v = tid + j * 256, q = v & 7, n = v >> 3;
        bSrc[j] = B + (size_t)(n0 + n) * K + q * 4;
        bDst[j] = sb + 16384u + (uint32_t)(n * 128) + (uint32_t)((q ^ (n & 7)) << 4);
    }

    float acc[4][8][4];
#pragma unroll
    for (int mf = 0; mf < 4; mf++)
#pragma unroll
        for (int nf = 0; nf < 8; nf++)
#pragma unroll
            for (int r = 0; r < 4; r++) acc[mf][nf][r] = 0.f;

    // ---- prologue: stage 0 into buf 0 ----
#pragma unroll
    for (int j = 0; j < 4; j++) CP_ASYNC16(aDst[j], aSrc[j]);
#pragma unroll
    for (int j = 0; j < 8; j++) CP_ASYNC16(bDst[j], bSrc[j]);
    CP_COMMIT();

    // ---- fragment address components ----
    int arow[4];
#pragma unroll
    for (int mf = 0; mf < 4; mf++)
        arow[mf] = wm * 64 + mf * 16 + (lane & 7) + ((lane >> 3) & 1) * 8;
    int aci = lane >> 4;           // 0..1: k-chunk select for x4
    int brow[8];
#pragma unroll
    for (int nf = 0; nf < 8; nf++)
        brow[nf] = wn * 64 + nf * 8 + (lane & 7);
    int bci = (lane >> 3) & 1;     // k-chunk select for x2

    int NT = K / 32;
    for (int t = 0; t < NT; t++) {
        int buf = t & 1;
        if (t + 1 < NT) {
            uint32_t bo = (uint32_t)(buf ^ 1) * 49152u;
            int kof = (t + 1) * 32;
#pragma unroll
            for (int j = 0; j < 4; j++) CP_ASYNC16(aDst[j] + bo, aSrc[j] + kof);
#pragma unroll
            for (int j = 0; j < 8; j++) CP_ASYNC16(bDst[j] + bo, bSrc[j] + kof);
            CP_COMMIT();
            CP_WAIT1();            // stage t's group complete
        } else {
            CP_WAIT0();
        }
        __syncthreads();

        uint32_t As = sb + (uint32_t)buf * 49152u;
        uint32_t Bs = As + 16384u;
#pragma unroll
        for (int ks = 0; ks < 4; ks++) {
            uint32_t a[4][4];
#pragma unroll
            for (int mf = 0; mf < 4; mf++) {
                uint32_t ad = As + (uint32_t)(arow[mf] * 128)
                            + (uint32_t)((((2 * ks + aci) ^ (arow[mf] & 7))) << 4);
                LDSM_X4(a[mf], ad);
            }
            uint32_t b[8][2];
#pragma unroll
            for (int nf = 0; nf < 8; nf++) {
                uint32_t bd = Bs + (uint32_t)(brow[nf] * 128)
                            + (uint32_t)((((2 * ks + bci) ^ (brow[nf] & 7))) << 4);
                LDSM_X2(b[nf], bd);
            }
#pragma unroll
            for (int mf = 0; mf < 4; mf++)
#pragma unroll
                for (int nf = 0; nf < 8; nf++)
                    MMA_TF32(acc[mf][nf], a[mf], b[nf]);
        }
        __syncthreads();           // protect buf before next-iter overwrite
    }

    // ---- epilogue: raw fp32 store ----
#pragma unroll
    for (int mf = 0; mf < 4; mf++) {
        int r0 = wm * 64 + mf * 16 + (lane >> 2);
#pragma unroll
        for (int half = 0; half < 2; half++) {
            int rr = r0 + half * 8;
            if (m0 + rr < Me) {
                size_t rowoff = (size_t)(base + m0 + rr) * Ntot;
#pragma unroll
                for (int nf = 0; nf < 8; nf++) {
                    int cc = n0 + wn * 64 + nf * 8 + (lane & 3) * 2;
                    float2 v = make_float2(acc[mf][nf][half * 2 + 0],
                                           acc[mf][nf][half * 2 + 1]);
                    *reinterpret_cast<float2*>(C + rowoff + cc) = v;
                }
            }
        }
    }
}

// ---------------- silu(t1)*t3 -> g_h (tf32) ----------------
__global__ void silu_mul_kernel() {
    size_t i = ((size_t)blockIdx.x * blockDim.x + threadIdx.x) * 4;
    float4 z4 = *reinterpret_cast<const float4*>(g_t1 + i);
    float4 u4 = *reinterpret_cast<const float4*>(g_t3 + i);
    uint4 h;
    float z;
    z = z4.x; h.x = f2tf32(z / (1.f + __expf(-z)) * u4.x);
    z = z4.y; h.y = f2tf32(z / (1.f + __expf(-z)) * u4.y);
    z = z4.z; h.z = f2tf32(z / (1.f + __expf(-z)) * u4.z);
    z = z4.w; h.w = f2tf32(z / (1.f + __expf(-z)) * u4.w);
    *reinterpret_cast<uint4*>(g_h + i) = h;
}

// ---------------- combine: out[t] = p0*y[pos0] + p1*y[pos1] ----------------
__global__ void combine_kernel(float* __restrict__ out) {
    int t = blockIdx.x;
    float p0 = g_prob[2 * t], p1 = g_prob[2 * t + 1];
    int   q0 = g_tokpos[2 * t], q1 = g_tokpos[2 * t + 1];
    int i = threadIdx.x * 4;
    float4 a = *reinterpret_cast<const float4*>(g_y + (size_t)q0 * D_DIM + i);
    float4 b = *reinterpret_cast<const float4*>(g_y + (size_t)q1 * D_DIM + i);
    float4 o;
    o.x = p0 * a.x + p1 * b.x;
    o.y = p0 * a.y + p1 * b.y;
    o.z = p0 * a.z + p1 * b.z;
    o.w = p0 * a.w + p1 * b.w;
    *reinterpret_cast<float4*>(out + (size_t)t * D_DIM + i) = o;
}

// ---------------- launch ----------------
extern "C" void kernel_launch(void* const* d_in, const int* in_sizes, int n_in,
                              void* d_out, int out_size) {
    const float* x  = (const float*)d_in[0];   // (B,S,D)
    const float* wg = (const float*)d_in[1];   // (D,E)
    const float* w1 = (const float*)d_in[2];   // (E,D,H)
    const float* w3 = (const float*)d_in[3];   // (E,D,H)
    const float* w2 = (const float*)d_in[4];   // (E,H,D)
    float* out = (float*)d_out;
    (void)in_sizes; (void)n_in; (void)out_size;

    cudaFuncSetAttribute(gemm_mma, cudaFuncAttributeMaxDynamicSharedMemorySize, GM_SMEM);

    // resolve device-global addresses (host calls; idempotent; capture-safe)
    void *p_xc, *p_t1, *p_t3, *p_h, *p_y, *p_w1T, *p_w3T, *p_w2T;
    cudaGetSymbolAddress(&p_xc,  g_xc);
    cudaGetSymbolAddress(&p_t1,  g_t1);
    cudaGetSymbolAddress(&p_t3,  g_t3);
    cudaGetSymbolAddress(&p_h,   g_h);
    cudaGetSymbolAddress(&p_y,   g_y);
    cudaGetSymbolAddress(&p_w1T, g_w1T);
    cudaGetSymbolAddress(&p_w3T, g_w3T);
    cudaGetSymbolAddress(&p_w2T, g_w2T);

    init_kernel<<<1, 32>>>();
    cvt_x_kernel<<<(T_TOK * D_DIM / 4) / 256, 256>>>(x);

    dim3 tb(32, 8);
    transpose_cvt_kernel<<<dim3(H_DIM / 32, D_DIM / 32, E_NUM), tb>>>(w1, (float*)p_w1T, D_DIM, H_DIM);
    transpose_cvt_kernel<<<dim3(H_DIM / 32, D_DIM / 32, E_NUM), tb>>>(w3, (float*)p_w3T, D_DIM, H_DIM);
    transpose_cvt_kernel<<<dim3(D_DIM / 32, H_DIM / 32, E_NUM), tb>>>(w2, (float*)p_w2T, H_DIM, D_DIM);

    gate_kernel<<<(T_TOK * 32 + 255) / 256, 256>>>(x, wg);
    offsets_kernel<<<1, 32>>>();
    scatter_kernel<<<(T_TOK + 255) / 256, 256>>>();

    // GEMM1: t1 = Xg @ W1^T-rows, t3 = Xg @ W3^T-rows   (z: 8 nblocks x {w1,w3})
    dim3 g1(NA / 128, E_NUM, 16);
    gemm_mma<<<g1, 256, GM_SMEM>>>((const float*)p_xc,
                                   (const float*)p_w1T, (const float*)p_w3T,
                                   (float*)p_t1, (float*)p_t3,
                                   D_DIM, H_DIM, 8, 1);

    silu_mul_kernel<<<(int)(((size_t)NA * H_DIM / 4) / 256), 256>>>();

    // GEMM2: y = h @ W2^T-rows
    dim3 g2(NA / 128, E_NUM, 4);
    gemm_mma<<<g2, 256, GM_SMEM>>>((const float*)p_h,
                                   (const float*)p_w2T, (const float*)p_w2T,
                                   (float*)p_y, (float*)p_y,
                                   H_DIM, D_DIM, 4, 0);

    combine_kernel<<<T_TOK, 256>>>(out);
}